// round 15
// baseline (speedup 1.0000x reference)
#include <cuda_runtime.h>

// Fixed problem shape
#define BB   4
#define CC   256
#define HH   128
#define WW   256
#define NGRP 4
#define CG   64      // channels per group
#define WIN  9       // window taps (1 x 9)
#define CK   32      // channel chunk held in smem
#define SRS  272     // padded smem row stride; 272 % 32 == 16 -> conflict-free paired LDS.64
                     // pixel p lives at col p+4 (replicate pad 4 each side)

__global__ __launch_bounds__(256, 3)
void crestereo_pairshfl_kernel(const float* __restrict__ left,
                               const float* __restrict__ right,
                               const float* __restrict__ flow,
                               float* __restrict__ out)
{
    __shared__ float srw[CK][SRS];   // 34,816 B/block -> 3 blocks = 104 KB/SM (L1D ~124 KB)

    const int bh = blockIdx.x;
    const int b  = bh >> 7;          // bh / HH
    const int h  = bh & (HH - 1);
    const int w  = threadIdx.x;
    const int HW = HH * WW;

    // ---- per-pixel bilinear setup (identical math to R1) ----
    const float fx = flow[(((size_t)b * 2 + 0) * HH + h) * WW + w];
    const float fy = flow[(((size_t)b * 2 + 1) * HH + h) * WW + w];
    const float x = (float)w + fx;
    const float y = (float)h + fy;
    const float x0f = floorf(x);
    const float y0f = floorf(y);
    const int ix0 = (int)x0f;
    const int iy0 = (int)y0f;
    const float ax = x - x0f;
    const float ay = y - y0f;

    float w00 = (1.f - ax) * (1.f - ay);
    float w01 = ax * (1.f - ay);
    float w10 = (1.f - ax) * ay;
    float w11 = ax * ay;

    const bool vx0 = (ix0     >= 0) & (ix0     <= WW - 1);
    const bool vx1 = (ix0 + 1 >= 0) & (ix0 + 1 <= WW - 1);
    const bool vy0 = (iy0     >= 0) & (iy0     <= HH - 1);
    const bool vy1 = (iy0 + 1 >= 0) & (iy0 + 1 <= HH - 1);
    if (!(vx0 & vy0)) w00 = 0.f;
    if (!(vx1 & vy0)) w01 = 0.f;
    if (!(vx0 & vy1)) w10 = 0.f;
    if (!(vx1 & vy1)) w11 = 0.f;

    const int x0c = min(max(ix0, 0), WW - 1);
    const int x1c = min(max(ix0 + 1, 0), WW - 1);
    const int y0c = min(max(iy0, 0), HH - 1);
    const int y1c = min(max(iy0 + 1, 0), HH - 1);

    const int o00 = y0c * WW + x0c;
    const int o01 = y0c * WW + x1c;
    const int o10 = y1c * WW + x0c;
    const int o11 = y1c * WW + x1c;

    // pair-consume identity: pixel pair pg (pixels 2pg, 2pg+1) in SAME warp
    const int pg   = w >> 1;
    const int cs   = w & 1;                 // channel parity handled by this thread
    const int lane = w & 31;
    const int src  = lane & ~1;             // even lane of this pixel pair

    const float* lbase = left  + (size_t)b * CC * HW + (size_t)h * WW + w;
    const float* rbase = right + (size_t)b * CC * HW;

    float macc[WIN];   // merged per-pixel accumulators (only these live in phase 1)

    for (int g = 0; g < NGRP; ++g) {
#pragma unroll
        for (int k = 0; k < WIN; ++k) macc[k] = 0.f;

        for (int ch0 = g * CG; ch0 < (g + 1) * CG; ch0 += CK) {
            __syncthreads();   // protect previous chunk's readers

            // ---- phase 1: burst-gather CK channels (EXACT R1 shape, 9 live accs) ----
#pragma unroll
            for (int cc = 0; cc < CK; ++cc) {
                const float* rb = rbase + (size_t)(ch0 + cc) * HW;
                float v = rb[o00] * w00;
                v = fmaf(rb[o01], w01, v);
                v = fmaf(rb[o10], w10, v);
                v = fmaf(rb[o11], w11, v);
                srw[cc][4 + w] = v;
                if (w == 0) {
                    srw[cc][0] = v; srw[cc][1] = v; srw[cc][2] = v; srw[cc][3] = v;
                }
                if (w == WW - 1) {
                    srw[cc][WW + 4] = v; srw[cc][WW + 5] = v;
                    srw[cc][WW + 6] = v; srw[cc][WW + 7] = v;
                }
            }
            __syncthreads();

            // ---- phase 2: pixel-pair consume; left pairs via warp shuffle ----
            float acc0[WIN], acc1[WIN];
#pragma unroll
            for (int k = 0; k < WIN; ++k) { acc0[k] = 0.f; acc1[k] = 0.f; }

#pragma unroll
            for (int i = 0; i < CK / 2; ++i) {
                // coalesced left loads: two consecutive channels at own pixel
                const float a = lbase[(size_t)(ch0 + 2 * i)     * HW];
                const float bv = lbase[(size_t)(ch0 + 2 * i + 1) * HW];
                // redistribute: left[2i+cs][2pg], left[2i+cs][2pg+1]
                const float A0 = __shfl_sync(0xffffffffu, a,  src);
                const float A1 = __shfl_sync(0xffffffffu, a,  src + 1);
                const float B0 = __shfl_sync(0xffffffffu, bv, src);
                const float B1 = __shfl_sync(0xffffffffu, bv, src + 1);
                const float lvx = cs ? B0 : A0;   // left[ch][2pg]
                const float lvy = cs ? B1 : A1;   // left[ch][2pg+1]

                // 10-float shared window via 5x LDS.64 (conflict-free at SRS=272)
                const float* sp = &srw[2 * i + cs][2 * pg];
                float tb[10];
#pragma unroll
                for (int j = 0; j < 5; ++j) {
                    const float2 d = *(const float2*)(sp + 2 * j);
                    tb[2 * j]     = d.x;
                    tb[2 * j + 1] = d.y;
                }
#pragma unroll
                for (int k = 0; k < WIN; ++k) {
                    acc0[k] = fmaf(lvx, tb[k],     acc0[k]);
                    acc1[k] = fmaf(lvy, tb[k + 1], acc1[k]);
                }
            }

            // ---- per-chunk parity merge -> own-pixel running total (9 regs) ----
#pragma unroll
            for (int k = 0; k < WIN; ++k) {
                const float t0 = acc0[k] + __shfl_xor_sync(0xffffffffu, acc0[k], 1);
                const float t1 = acc1[k] + __shfl_xor_sync(0xffffffffu, acc1[k], 1);
                macc[k] += cs ? t1 : t0;
            }
        }

        // ---- write 9 output taps for this group (coalesced across w) ----
        const float scale = 1.f / (float)CG;
        float* ob = out + (((size_t)(b * NGRP + g) * WIN) * HH + h) * WW + w;
#pragma unroll
        for (int k = 0; k < WIN; ++k)
            ob[(size_t)k * HW] = macc[k] * scale;
    }
}

extern "C" void kernel_launch(void* const* d_in, const int* in_sizes, int n_in,
                              void* d_out, int out_size)
{
    const float* left  = (const float*)d_in[0];
    const float* right = (const float*)d_in[1];
    const float* flow  = (const float*)d_in[2];
    float* out = (float*)d_out;

    dim3 grid(BB * HH);   // 512 blocks, one per (b, h) row
    dim3 block(WW);       // 256 threads, one per w
    crestereo_pairshfl_kernel<<<grid, block>>>(left, right, flow, out);
}

// round 16
// speedup vs baseline: 2.4188x; 2.4188x over previous
#include <cuda_runtime.h>

// Fixed problem shape
#define BB   4
#define CC   256
#define HH   128
#define WW   256
#define NGRP 4
#define CG   64      // channels per group
#define WIN  9       // window taps (1 x 9)
#define CK   32      // channel chunk held in smem
#define BAT  8       // channels per explicit gather batch (32 LDGs in flight)

__global__ __launch_bounds__(256, 3)
void crestereo_r16_kernel(const float* __restrict__ left,
                          const float* __restrict__ right,
                          const float* __restrict__ flow,
                          float* __restrict__ out)
{
    __shared__ float srw[CK][WW];   // 32 KB -> 3 blocks/SM = 96 KB (L1D ~132 KB)

    const int bh = blockIdx.x;
    const int b  = bh >> 7;          // bh / HH
    const int h  = bh & (HH - 1);
    const int w  = threadIdx.x;
    const int HW = HH * WW;

    // ---- per-pixel bilinear setup (identical math to R1) ----
    const float fx = flow[(((size_t)b * 2 + 0) * HH + h) * WW + w];
    const float fy = flow[(((size_t)b * 2 + 1) * HH + h) * WW + w];
    const float x = (float)w + fx;
    const float y = (float)h + fy;
    const float x0f = floorf(x);
    const float y0f = floorf(y);
    const int ix0 = (int)x0f;
    const int iy0 = (int)y0f;
    const float ax = x - x0f;
    const float ay = y - y0f;

    float w00 = (1.f - ax) * (1.f - ay);
    float w01 = ax * (1.f - ay);
    float w10 = (1.f - ax) * ay;
    float w11 = ax * ay;

    const bool vx0 = (ix0     >= 0) & (ix0     <= WW - 1);
    const bool vx1 = (ix0 + 1 >= 0) & (ix0 + 1 <= WW - 1);
    const bool vy0 = (iy0     >= 0) & (iy0     <= HH - 1);
    const bool vy1 = (iy0 + 1 >= 0) & (iy0 + 1 <= HH - 1);
    if (!(vx0 & vy0)) w00 = 0.f;
    if (!(vx1 & vy0)) w01 = 0.f;
    if (!(vx0 & vy1)) w10 = 0.f;
    if (!(vx1 & vy1)) w11 = 0.f;

    const int x0c = min(max(ix0, 0), WW - 1);
    const int x1c = min(max(ix0 + 1, 0), WW - 1);
    const int y0c = min(max(iy0, 0), HH - 1);
    const int y1c = min(max(iy0 + 1, 0), HH - 1);

    const int o00 = y0c * WW + x0c;
    const int o01 = y0c * WW + x1c;
    const int o10 = y1c * WW + x0c;
    const int o11 = y1c * WW + x1c;

    // 9 replicate-clamped sliding-window indices (R1's zero-overhead scheme)
    int widx[WIN];
#pragma unroll
    for (int k = 0; k < WIN; ++k)
        widx[k] = min(max(w + k - 4, 0), WW - 1);

    const float* lbase = left  + (size_t)b * CC * HW + (size_t)h * WW + w;
    const float* rbase = right + (size_t)b * CC * HW;

    float acc[WIN];
    const float scale = 1.f / (float)CG;

    for (int g = 0; g < NGRP; ++g) {
#pragma unroll
        for (int k = 0; k < WIN; ++k) acc[k] = 0.f;

        for (int ch0 = g * CG; ch0 < (g + 1) * CG; ch0 += CK) {
            __syncthreads();   // protect previous chunk's readers

            // Per-chunk corner base pointers: all per-channel addresses become
            // compile-time immediate offsets (j*HW) off these four registers.
            const float* r00 = rbase + (size_t)ch0 * HW + o00;
            const float* r01 = rbase + (size_t)ch0 * HW + o01;
            const float* r10 = rbase + (size_t)ch0 * HW + o10;
            const float* r11 = rbase + (size_t)ch0 * HW + o11;

            // ---- phase 1: gather in explicit 8-channel batches (32 LDGs deep) ----
#pragma unroll
            for (int cb = 0; cb < CK; cb += BAT) {
                float t0[BAT], t1[BAT], t2[BAT], t3[BAT];
#pragma unroll
                for (int j = 0; j < BAT; ++j) {
                    t0[j] = r00[(cb + j) * HW];
                    t1[j] = r01[(cb + j) * HW];
                    t2[j] = r10[(cb + j) * HW];
                    t3[j] = r11[(cb + j) * HW];
                }
#pragma unroll
                for (int j = 0; j < BAT; ++j) {
                    float v = t0[j] * w00;
                    v = fmaf(t1[j], w01, v);
                    v = fmaf(t2[j], w10, v);
                    v = fmaf(t3[j], w11, v);
                    srw[cb + j][w] = v;
                }
            }
            __syncthreads();

            // ---- phase 2: R1's proven consume loop, immediate-offset left loads ----
            const float* lc = lbase + (size_t)ch0 * HW;
#pragma unroll
            for (int cc = 0; cc < CK; ++cc) {
                const float lv = lc[cc * HW];
#pragma unroll
                for (int k = 0; k < WIN; ++k)
                    acc[k] = fmaf(lv, srw[cc][widx[k]], acc[k]);
            }
        }

        // ---- write 9 output taps for this group (coalesced across w) ----
        float* ob = out + (((size_t)(b * NGRP + g) * WIN) * HH + h) * WW + w;
#pragma unroll
        for (int k = 0; k < WIN; ++k)
            ob[(size_t)k * HW] = acc[k] * scale;
    }
}

extern "C" void kernel_launch(void* const* d_in, const int* in_sizes, int n_in,
                              void* d_out, int out_size)
{
    const float* left  = (const float*)d_in[0];
    const float* right = (const float*)d_in[1];
    const float* flow  = (const float*)d_in[2];
    float* out = (float*)d_out;

    dim3 grid(BB * HH);   // 512 blocks, one per (b, h) row
    dim3 block(WW);       // 256 threads, one per w
    crestereo_r16_kernel<<<grid, block>>>(left, right, flow, out);
}

// round 17
// speedup vs baseline: 2.4577x; 1.0161x over previous
#include <cuda_runtime.h>

// Fixed problem shape
#define BB   4
#define CC   256
#define HH   128
#define WW   256
#define NGRP 4
#define CG   64      // channels per group
#define WIN  9       // window taps (1 x 9)
#define CK   32      // channel chunk held in smem
#define BAT  8       // channels per explicit batch (gathers: 32 LDGs deep)

__global__ __launch_bounds__(256, 3)
void crestereo_r17_kernel(const float* __restrict__ left,
                          const float* __restrict__ right,
                          const float* __restrict__ flow,
                          float* __restrict__ out)
{
    __shared__ float srw[CK][WW];   // 32 KB -> 3 blocks/SM = 96 KB (L1D ~132 KB)

    const int bh = blockIdx.x;
    const int b  = bh >> 7;          // bh / HH
    const int h  = bh & (HH - 1);
    const int w  = threadIdx.x;
    const int HW = HH * WW;

    // ---- per-pixel bilinear setup (identical math to R16) ----
    const float fx = flow[(((size_t)b * 2 + 0) * HH + h) * WW + w];
    const float fy = flow[(((size_t)b * 2 + 1) * HH + h) * WW + w];
    const float x = (float)w + fx;
    const float y = (float)h + fy;
    const float x0f = floorf(x);
    const float y0f = floorf(y);
    const int ix0 = (int)x0f;
    const int iy0 = (int)y0f;
    const float ax = x - x0f;
    const float ay = y - y0f;

    float w00 = (1.f - ax) * (1.f - ay);
    float w01 = ax * (1.f - ay);
    float w10 = (1.f - ax) * ay;
    float w11 = ax * ay;

    const bool vx0 = (ix0     >= 0) & (ix0     <= WW - 1);
    const bool vx1 = (ix0 + 1 >= 0) & (ix0 + 1 <= WW - 1);
    const bool vy0 = (iy0     >= 0) & (iy0     <= HH - 1);
    const bool vy1 = (iy0 + 1 >= 0) & (iy0 + 1 <= HH - 1);
    if (!(vx0 & vy0)) w00 = 0.f;
    if (!(vx1 & vy0)) w01 = 0.f;
    if (!(vx0 & vy1)) w10 = 0.f;
    if (!(vx1 & vy1)) w11 = 0.f;

    const int x0c = min(max(ix0, 0), WW - 1);
    const int x1c = min(max(ix0 + 1, 0), WW - 1);
    const int y0c = min(max(iy0, 0), HH - 1);
    const int y1c = min(max(iy0 + 1, 0), HH - 1);

    const int o00 = y0c * WW + x0c;
    const int o01 = y0c * WW + x1c;
    const int o10 = y1c * WW + x0c;
    const int o11 = y1c * WW + x1c;

    // 9 replicate-clamped sliding-window indices (zero per-channel overhead)
    int widx[WIN];
#pragma unroll
    for (int k = 0; k < WIN; ++k)
        widx[k] = min(max(w + k - 4, 0), WW - 1);

    const float* lbase = left  + (size_t)b * CC * HW + (size_t)h * WW + w;
    const float* rbase = right + (size_t)b * CC * HW;

    float acc[WIN];
    const float scale = 1.f / (float)CG;

    for (int g = 0; g < NGRP; ++g) {
#pragma unroll
        for (int k = 0; k < WIN; ++k) acc[k] = 0.f;

        for (int ch0 = g * CG; ch0 < (g + 1) * CG; ch0 += CK) {
            __syncthreads();   // protect previous chunk's readers

            // Per-chunk base pointers: per-channel addresses fold into
            // compile-time immediate offsets (j*HW) off these registers.
            const float* r00 = rbase + (size_t)ch0 * HW + o00;
            const float* r01 = rbase + (size_t)ch0 * HW + o01;
            const float* r10 = rbase + (size_t)ch0 * HW + o10;
            const float* r11 = rbase + (size_t)ch0 * HW + o11;
            const float* lc  = lbase + (size_t)ch0 * HW;

            // ---- phase 1: gather in explicit 8-channel batches (32 LDGs deep) ----
#pragma unroll
            for (int cb = 0; cb < CK; cb += BAT) {
                float t0[BAT], t1[BAT], t2[BAT], t3[BAT];
#pragma unroll
                for (int j = 0; j < BAT; ++j) {
                    t0[j] = r00[(cb + j) * HW];
                    t1[j] = r01[(cb + j) * HW];
                    t2[j] = r10[(cb + j) * HW];
                    t3[j] = r11[(cb + j) * HW];
                }
#pragma unroll
                for (int j = 0; j < BAT; ++j) {
                    float v = t0[j] * w00;
                    v = fmaf(t1[j], w01, v);
                    v = fmaf(t2[j], w10, v);
                    v = fmaf(t3[j], w11, v);
                    srw[cb + j][w] = v;
                }
            }

            // ---- pre-barrier left prefetch: first 8 channels of this chunk.
            //      t-arrays are dead here, so these reuse registers; the loads'
            //      latency hides behind barrier drain instead of stalling
            //      phase 2's first FMAs. (LDGs can't be hoisted across BAR.)
            float lv[BAT];
#pragma unroll
            for (int j = 0; j < BAT; ++j)
                lv[j] = lc[j * HW];

            __syncthreads();

            // ---- phase 2: consume; channels 0-7 use prefetched lv ----
#pragma unroll
            for (int j = 0; j < BAT; ++j) {
#pragma unroll
                for (int k = 0; k < WIN; ++k)
                    acc[k] = fmaf(lv[j], srw[j][widx[k]], acc[k]);
            }

            // channels 8-31: explicit lv batches (no barrier in the way,
            // so these batch and hoist freely)
#pragma unroll
            for (int cb = BAT; cb < CK; cb += BAT) {
                float lw[BAT];
#pragma unroll
                for (int j = 0; j < BAT; ++j)
                    lw[j] = lc[(cb + j) * HW];
#pragma unroll
                for (int j = 0; j < BAT; ++j) {
#pragma unroll
                    for (int k = 0; k < WIN; ++k)
                        acc[k] = fmaf(lw[j], srw[cb + j][widx[k]], acc[k]);
                }
            }
        }

        // ---- write 9 output taps for this group (coalesced across w) ----
        float* ob = out + (((size_t)(b * NGRP + g) * WIN) * HH + h) * WW + w;
#pragma unroll
        for (int k = 0; k < WIN; ++k)
            ob[(size_t)k * HW] = acc[k] * scale;
    }
}

extern "C" void kernel_launch(void* const* d_in, const int* in_sizes, int n_in,
                              void* d_out, int out_size)
{
    const float* left  = (const float*)d_in[0];
    const float* right = (const float*)d_in[1];
    const float* flow  = (const float*)d_in[2];
    float* out = (float*)d_out;

    dim3 grid(BB * HH);   // 512 blocks, one per (b, h) row
    dim3 block(WW);       // 256 threads, one per w
    crestereo_r17_kernel<<<grid, block>>>(left, right, flow, out);
}